// round 12
// baseline (speedup 1.0000x reference)
#include <cuda_runtime.h>
#include <math_constants.h>
#include <cooperative_groups.h>

#define WIN    400
#define RNUM   64
#define BNUM   2
#define ANUM   3
#define KSEL   8
#define WPC    4                  // windows per tile
#define SPAN   (WIN * WPC)        // 1600 floats
#define NV4S   (SPAN / 4)         // 400 vec4 per row span
#define NFULL  12                 // full warp-iterations (12*32 = 384)
#define RPC    32                 // ref rows per CTA (cluster of 2 covers 64)
#define RPW    4                  // rows per warp

namespace cg = cooperative_groups;

__global__ __launch_bounds__(256, 6) __cluster_dims__(2, 1, 1)
void win_topk_kernel(
    const float* __restrict__ mixed,    // [B, S]
    const float* __restrict__ ref,      // [A, R, S]
    const float* __restrict__ weights,  // [K]
    float* __restrict__ out,            // [6*W] scores ++ [6*W*K] idx (as float)
    int S, int W, int write_idx)
{
    const int rank = blockIdx.x;        // 0,1: row half (cluster rank)
    const int wg   = blockIdx.y;        // window-group (4 windows), 0..249
    const int a    = blockIdx.z;
    const int tid  = threadIdx.x;
    const int warp = tid >> 5;
    const int lane = tid & 31;

    __shared__ __align__(16) float sm_mixed[BNUM][SPAN];
    __shared__ float sm_scores[BNUM][WPC][RNUM];   // rank0's copy is authoritative
    __shared__ float sm_w[KSEL];

    cg::cluster_group cluster = cg::this_cluster();
    float* dst_scores = (float*)cluster.map_shared_rank((void*)sm_scores, 0);

    const long base = (long)wg * SPAN;

    // Stage mixed span (both batch rows) into shared, vectorized.
    {
        const float4* m4 = (const float4*)mixed;
        float4* sm4 = (float4*)&sm_mixed[0][0];
        for (int i = tid; i < BNUM * NV4S; i += 256) {   // 800 vec4
            int b = i / NV4S, v = i % NV4S;
            sm4[i] = m4[((long)b * S + base) / 4 + v];
        }
        if (tid < KSEL) sm_w[tid] = weights[tid];
    }
    __syncthreads();

    // Each warp streams 4 ref rows at 6.4 KB contiguous each.
    {
        const float4* sm0 = (const float4*)&sm_mixed[0][0];
        const float4* sm1 = (const float4*)&sm_mixed[1][0];
        const float* refa = ref + ((long)a * RNUM + rank * RPC) * S + base;

        #pragma unroll
        for (int i = 0; i < RPW; i++) {
            const int rl = warp * RPW + i;               // local row 0..31
            const int r  = rank * RPC + rl;              // global row 0..63
            const float4* row4 = (const float4*)(refa + (long)rl * S);

            float sA[WPC] = {0.f, 0.f, 0.f, 0.f};   // batch 0, windows 0..3
            float sB[WPC] = {0.f, 0.f, 0.f, 0.f};   // batch 1, windows 0..3

            #pragma unroll
            for (int j = 0; j < NFULL; j++) {        // 384 vec4, full warp
                const int v = lane + j * 32;
                float4 rv = __ldcs(&row4[v]);
                float4 m0 = sm0[v];
                float4 m1 = sm1[v];
                float c0 = rv.x * m0.x;
                c0 = fmaf(rv.y, m0.y, c0);
                c0 = fmaf(rv.z, m0.z, c0);
                c0 = fmaf(rv.w, m0.w, c0);
                float c1 = rv.x * m1.x;
                c1 = fmaf(rv.y, m1.y, c1);
                c1 = fmaf(rv.z, m1.z, c1);
                c1 = fmaf(rv.w, m1.w, c1);
                // Window boundaries at v = 100, 200, 300 (static per j).
                const int wlo = (j * 32) / (WIN / 4);
                const int whi = (j * 32 + 31) / (WIN / 4);
                if (wlo == whi) {
                    sA[wlo] += c0; sB[wlo] += c1;
                } else if (v < whi * (WIN / 4)) {
                    sA[wlo] += c0; sB[wlo] += c1;
                } else {
                    sA[whi] += c0; sB[whi] += c1;
                }
            }
            if (lane < NV4S - NFULL * 32) {          // tail: v=384..399, win 3
                const int v = NFULL * 32 + lane;
                float4 rv = __ldcs(&row4[v]);
                float4 m0 = sm0[v];
                float4 m1 = sm1[v];
                float c0 = rv.x * m0.x;
                c0 = fmaf(rv.y, m0.y, c0);
                c0 = fmaf(rv.z, m0.z, c0);
                c0 = fmaf(rv.w, m0.w, c0);
                float c1 = rv.x * m1.x;
                c1 = fmaf(rv.y, m1.y, c1);
                c1 = fmaf(rv.z, m1.z, c1);
                c1 = fmaf(rv.w, m1.w, c1);
                sA[WPC - 1] += c0; sB[WPC - 1] += c1;
            }
            // Warp reductions (8 values)
            #pragma unroll
            for (int win = 0; win < WPC; win++) {
                #pragma unroll
                for (int off = 16; off > 0; off >>= 1) {
                    sA[win] += __shfl_down_sync(0xffffffffu, sA[win], off);
                    sB[win] += __shfl_down_sync(0xffffffffu, sB[win], off);
                }
            }
            if (lane == 0) {
                #pragma unroll
                for (int win = 0; win < WPC; win++) {
                    dst_scores[(0 * WPC + win) * RNUM + r] = sA[win] * (1.0f / WIN);
                    dst_scores[(1 * WPC + win) * RNUM + r] = sB[win] * (1.0f / WIN);
                }
            }
        }
    }

    // All scores (both halves) land in rank0's smem; barrier cluster-wide.
    cluster.sync();

    // Rank 0: top-K (K=8) over 64 refs; warps 0..7 handle the 8 (b,win) combos.
    if (rank == 0) {
        const int b   = warp >> 2;
        const int win = warp & 3;
        float v0 = sm_scores[b][win][lane];
        float v1 = sm_scores[b][win][lane + 32];
        float acc = 0.f;

        const int  wglob = wg * WPC + win;
        const long ow    = ((long)b * ANUM + a) * W + wglob;
        const long ibase = (long)BNUM * ANUM * W + ow * KSEL;

        #pragma unroll
        for (int k = 0; k < KSEL; k++) {
            float bv; int bi;
            if (v0 >= v1) { bv = v0; bi = lane; }        // ties -> lower index
            else          { bv = v1; bi = lane + 32; }
            #pragma unroll
            for (int off = 16; off > 0; off >>= 1) {
                float ov = __shfl_xor_sync(0xffffffffu, bv, off);
                int   oi = __shfl_xor_sync(0xffffffffu, bi, off);
                if (ov > bv || (ov == bv && oi < bi)) { bv = ov; bi = oi; }
            }
            acc = fmaf(bv, sm_w[k], acc);
            if (write_idx && lane == 0) out[ibase + k] = (float)bi;
            if (bi == lane)      v0 = -CUDART_INF_F;
            if (bi == lane + 32) v1 = -CUDART_INF_F;
        }
        if (lane == 0) out[ow] = acc;
    }
}

extern "C" void kernel_launch(void* const* d_in, const int* in_sizes, int n_in,
                              void* d_out, int out_size) {
    const float* mixed   = (const float*)d_in[0];
    const float* ref     = (const float*)d_in[1];
    const float* weights = (const float*)d_in[2];
    float* out = (float*)d_out;

    const int S = in_sizes[0] / BNUM;      // 400000
    const int W = S / WIN;                 // 1000
    const int write_idx = (out_size >= BNUM * ANUM * W * (1 + KSEL)) ? 1 : 0;

    dim3 grid(2, W / WPC, ANUM);           // (2, 250, 3) = 1500 CTAs, 750 clusters
    win_topk_kernel<<<grid, 256>>>(mixed, ref, weights, out, S, W, write_idx);
}

// round 13
// speedup vs baseline: 1.1890x; 1.1890x over previous
#include <cuda_runtime.h>
#include <math_constants.h>

#define WIN   400
#define RNUM  64
#define BNUM  2
#define ANUM  3
#define KSEL  8
#define WPC   2                 // windows per CTA
#define SPAN  (WIN * WPC)       // 800 floats
#define NV4S  (SPAN / 4)        // 200 float4 per row span
#define NTHR  128
#define NWARP (NTHR / 32)       // 4
#define RPW   (RNUM / NWARP)    // 16 rows per warp

__global__ __launch_bounds__(NTHR, 12) void win_topk_kernel(
    const float* __restrict__ mixed,    // [B, S]
    const float* __restrict__ ref,      // [A, R, S]
    const float* __restrict__ weights,  // [K]
    float* __restrict__ out,            // [6*W] scores ++ [6*W*K] idx (as float)
    int S, int W, int write_idx)
{
    const int wg   = blockIdx.x;        // window-pair index
    const int a    = blockIdx.y;
    const int tid  = threadIdx.x;
    const int warp = tid >> 5;
    const int lane = tid & 31;

    __shared__ __align__(16) float sm_mixed[BNUM][SPAN];
    __shared__ float sm_scores[BNUM][WPC][RNUM];
    __shared__ float sm_w[KSEL];

    const long base = (long)wg * SPAN;

    // Stage mixed span (both batch rows) into shared, vectorized.
    {
        const float4* m4 = (const float4*)mixed;  // S % 4 == 0, base % 4 == 0
        float4* sm4 = (float4*)&sm_mixed[0][0];
        for (int i = tid; i < BNUM * NV4S; i += NTHR) {   // 400 float4
            int b = i / NV4S, v = i % NV4S;
            sm4[i] = m4[((long)b * S + base) / 4 + v];
        }
        if (tid < KSEL) sm_w[tid] = weights[tid];
    }
    __syncthreads();

    // Each warp streams 16 ref rows over the 3200B span (2 windows, 2 batches).
    {
        const float4* sm0 = (const float4*)&sm_mixed[0][0];
        const float4* sm1 = (const float4*)&sm_mixed[1][0];
        const float* refa = ref + ((long)a * RNUM) * S + base;

        for (int i = 0; i < RPW; i++) {
            const int r = warp * RPW + i;
            const float4* row4 = (const float4*)(refa + (long)r * S);

            float s00 = 0.f, s01 = 0.f;   // batch0: win0, win1
            float s10 = 0.f, s11 = 0.f;   // batch1: win0, win1
            #pragma unroll
            for (int j = 0; j < 6; j++) {   // 192 vec4 full-warp
                int v = lane + j * 32;
                float4 rv = __ldcs(&row4[v]);
                float4 m0 = sm0[v];
                float4 m1 = sm1[v];
                float c0 = rv.x * m0.x;
                c0 = fmaf(rv.y, m0.y, c0);
                c0 = fmaf(rv.z, m0.z, c0);
                c0 = fmaf(rv.w, m0.w, c0);
                float c1 = rv.x * m1.x;
                c1 = fmaf(rv.y, m1.y, c1);
                c1 = fmaf(rv.z, m1.z, c1);
                c1 = fmaf(rv.w, m1.w, c1);
                if (v < WIN / 4) { s00 += c0; s10 += c1; }
                else             { s01 += c0; s11 += c1; }
            }
            if (lane < NV4S - 192) {        // tail: vec4 192..199 (all win1)
                int v = 192 + lane;
                float4 rv = __ldcs(&row4[v]);
                float4 m0 = sm0[v];
                float4 m1 = sm1[v];
                float c0 = rv.x * m0.x;
                c0 = fmaf(rv.y, m0.y, c0);
                c0 = fmaf(rv.z, m0.z, c0);
                c0 = fmaf(rv.w, m0.w, c0);
                float c1 = rv.x * m1.x;
                c1 = fmaf(rv.y, m1.y, c1);
                c1 = fmaf(rv.z, m1.z, c1);
                c1 = fmaf(rv.w, m1.w, c1);
                s01 += c0; s11 += c1;
            }
            // Warp reductions (4 values)
            #pragma unroll
            for (int off = 16; off > 0; off >>= 1) {
                s00 += __shfl_down_sync(0xffffffffu, s00, off);
                s01 += __shfl_down_sync(0xffffffffu, s01, off);
                s10 += __shfl_down_sync(0xffffffffu, s10, off);
                s11 += __shfl_down_sync(0xffffffffu, s11, off);
            }
            if (lane == 0) {
                sm_scores[0][0][r] = s00 * (1.0f / WIN);
                sm_scores[0][1][r] = s01 * (1.0f / WIN);
                sm_scores[1][0][r] = s10 * (1.0f / WIN);
                sm_scores[1][1][r] = s11 * (1.0f / WIN);
            }
        }
    }
    __syncthreads();

    // Top-K (K=8) over 64 refs; warps 0..3 handle the 4 (b, win) combos.
    {
        const int b   = warp >> 1;
        const int win = warp & 1;
        float v0 = sm_scores[b][win][lane];
        float v1 = sm_scores[b][win][lane + 32];
        float acc = 0.f;

        const int  wglob = wg * WPC + win;
        const long ow    = ((long)b * ANUM + a) * W + wglob;
        const long ibase = (long)BNUM * ANUM * W + ow * KSEL;

        #pragma unroll
        for (int k = 0; k < KSEL; k++) {
            float bv; int bi;
            if (v0 >= v1) { bv = v0; bi = lane; }        // ties -> lower index
            else          { bv = v1; bi = lane + 32; }
            #pragma unroll
            for (int off = 16; off > 0; off >>= 1) {
                float ov = __shfl_xor_sync(0xffffffffu, bv, off);
                int   oi = __shfl_xor_sync(0xffffffffu, bi, off);
                if (ov > bv || (ov == bv && oi < bi)) { bv = ov; bi = oi; }
            }
            acc = fmaf(bv, sm_w[k], acc);
            if (write_idx && lane == 0) out[ibase + k] = (float)bi;
            if (bi == lane)      v0 = -CUDART_INF_F;
            if (bi == lane + 32) v1 = -CUDART_INF_F;
        }
        if (lane == 0) out[ow] = acc;
    }
}

extern "C" void kernel_launch(void* const* d_in, const int* in_sizes, int n_in,
                              void* d_out, int out_size) {
    const float* mixed   = (const float*)d_in[0];
    const float* ref     = (const float*)d_in[1];
    const float* weights = (const float*)d_in[2];
    float* out = (float*)d_out;

    const int S = in_sizes[0] / BNUM;      // 400000
    const int W = S / WIN;                 // 1000
    const int write_idx = (out_size >= BNUM * ANUM * W * (1 + KSEL)) ? 1 : 0;

    dim3 grid(W / WPC, ANUM);              // (500, 3) = 1500 CTAs x 128 thr
    win_topk_kernel<<<grid, NTHR>>>(mixed, ref, weights, out, S, W, write_idx);
}